// round 13
// baseline (speedup 1.0000x reference)
#include <cuda_runtime.h>
#include <cuda_fp16.h>
#include <math.h>
#include <stdint.h>

// ---------------------------------------------------------------------------
// Problem constants: B=64, S=64, T=64, STEPS=32, E=512, H=512, G=256, V=32000
// ---------------------------------------------------------------------------
#define NB   64
#define NS   64
#define NT   64
#define NSTEPS 32
#define NE   512
#define NH   512
#define NG   256
#define NV   32000
#define H4   2048
#define H2   1024
#define H3   1536
#define CIW  3328   // E + 2H + 2H + G + H

#define GRID_PERS 128   // persistent-kernel grid (<=148 SMs -> co-resident)

// ---------------------------------------------------------------------------
// Scratch (device globals; no allocations allowed)
// ---------------------------------------------------------------------------
__device__ float d_src_e[NS*NB*NE];        // time-major [s][b][e]
__device__ float d_rat_e[NS*NB*NE];
__device__ float d_tgt_e[NT*NB*NE];        // [t][b][e]
__device__ float d_Xw[4][NS*NB*H4];        // x@Wih + b per lstm {srcF,srcB,ratF,ratB}
__device__ float d_hbuf[2][4][NB*NH];      // ping-pong h (encoder, fp32)
__device__ float d_enc[2][NB*NS*H2];       // [b][s][2H]; 0=src 1=rat
__device__ float d_P[2][NB*NS*H3];         // enc_out @ W1[:2H] + b1
__device__ float d_q[NB*H3];               // h @ W1[2H:]
__device__ float d_Abuf[2][NSTEPS*NB*H2];  // attention outputs A, Ar
__device__ float d_Dbuf[NSTEPS*NB*NH];     // decoder h per step
__device__ float d_tgtW[NSTEPS*NB*H4];     // tgt_e @ dec_Wih[:E] + dec_b
__device__ float d_hdec[2][NB*NH];
__device__ float d_cfin[NB*NH];            // encoder (src,fwd) final c
__device__ float d_gpart[4*NB*H4];         // decoder gemm partials (v-layout)
__device__ float d_ci[(size_t)NB*NT*CIW];
__device__ float d_hid[(size_t)NB*NT*H2];
// fragment-packed fp16 operand scratch (uint32 = half2)
__device__ uint32_t d_Ap[8*1024*1024];     // 32MB: slot0 @0, slot1 @4M
__device__ uint32_t d_Bp[(size_t)H2*NV/2]; // 65MB (max = cls_W2 in half2)
// recurrence tensor-core operands (packed fp16)
__device__ uint32_t d_hpk[2][4][NB*NH/2];  // encoder h, ping-pong, per lstm
__device__ uint32_t d_xpk[NB*2560/2];      // decoder [A,Ar,h] K=2560
__device__ uint32_t d_WhhPkF[NH*H4/2];     // gate-v-interleaved enc Whh fwd (2MB)
__device__ uint32_t d_WhhPkB[NH*H4/2];     // bwd
__device__ uint32_t d_WdecPk[2560*H4/2];   // [dec_Wih[512:]; dec_Whh] (10MB)
__device__ unsigned int g_bar = 0;

#define AP_SLOT1 (4u*1024u*1024u)

__device__ __forceinline__ float sigf(float x) { return 1.f / (1.f + expf(-x)); }

// Software grid barrier. All GRID_PERS blocks must be co-resident.
__device__ __forceinline__ void grid_bar() {
    __syncthreads();
    if (threadIdx.x == 0) {
        __threadfence();                       // release
        unsigned int t = atomicAdd(&g_bar, 1u);
        unsigned int target = t - (t & (GRID_PERS - 1u)) + GRID_PERS;
        unsigned int v;
        do {
            asm volatile("ld.acquire.gpu.global.u32 %0, [%1];"
                         : "=r"(v) : "l"(&g_bar) : "memory");
        } while (v < target);
    }
    __syncthreads();
}

__device__ __forceinline__ uint32_t f2h2(float lo, float hi) {
    __half2 h = __floats2half2_rn(lo, hi);
    return *reinterpret_cast<uint32_t*>(&h);
}

__device__ __forceinline__ uint32_t smem_addr_u32(const void* p) {
    uint32_t a;
    asm("{ .reg .u64 t; cvta.to.shared.u64 t, %1; cvt.u32.u64 %0, t; }"
        : "=r"(a) : "l"(p));
    return a;
}
__device__ __forceinline__ void cpasync16(uint32_t saddr, const void* g) {
    asm volatile("cp.async.ca.shared.global [%0], [%1], 16;"
                 :: "r"(saddr), "l"(g) : "memory");
}
#define CP_COMMIT() asm volatile("cp.async.commit_group;" ::: "memory")
#define CP_WAIT2()  asm volatile("cp.async.wait_group 2;" ::: "memory")

// u32 index inside a packed-A fp16 buffer with MS=4 m-slots (M=64), for the
// half2 holding elements (m, j) and (m, j+1); j must be even.
__device__ __forceinline__ uint32_t hpk_idx(int m, int j) {
    int ks = j >> 4;
    int t = (j >> 1) & 3;
    int khi = (j >> 3) & 1;
    int g = m & 7;
    int mhi = (m >> 3) & 1;
    int mslot = m >> 4;
    return (uint32_t)((((ks * 4 + mslot) * 32 + g * 4 + t) << 2) + mhi + (khi << 1));
}

#define MMA16F(accv, av, b0, b1)                                              \
    asm volatile(                                                             \
        "mma.sync.aligned.m16n8k16.row.col.f32.f16.f16.f32 "                  \
        "{%0,%1,%2,%3}, {%4,%5,%6,%7}, {%8,%9}, {%0,%1,%2,%3};"               \
        : "+f"((accv)[0]), "+f"((accv)[1]), "+f"((accv)[2]), "+f"((accv)[3])  \
        : "r"((av).x), "r"((av).y), "r"((av).z), "r"((av).w),                 \
          "r"(b0), "r"(b1))

// ---------------------------------------------------------------------------
// Operand pack kernels (fragment-ordered fp16, m16n8k16)
// ---------------------------------------------------------------------------
__global__ void packA_kernel(const float* __restrict__ A, uint32_t* __restrict__ Ap,
                             int M, int K, int lda) {
    int idx = blockIdx.x * 256 + threadIdx.x;
    int total = (K >> 4) * (M >> 4) * 32;
    if (idx >= total) return;
    int lane = idx & 31;
    int g = lane >> 2, t = lane & 3;
    int rest = idx >> 5;
    int MS = M >> 4;
    int mslot = rest % MS, ks = rest / MS;
    int m0 = mslot * 16 + g, k0 = ks * 16 + t * 2;
    const float* r0 = A + (size_t)m0 * lda;
    const float* r1 = A + (size_t)(m0 + 8) * lda;
    uint4 u;
    u.x = f2h2(r0[k0],     r0[k0 + 1]);
    u.y = f2h2(r1[k0],     r1[k0 + 1]);
    u.z = f2h2(r0[k0 + 8], r0[k0 + 9]);
    u.w = f2h2(r1[k0 + 8], r1[k0 + 9]);
    ((uint4*)Ap)[idx] = u;
}

__global__ void packB_kernel(const float* __restrict__ B, uint32_t* __restrict__ Bp,
                             int K, int N, int ldb) {
    int idx = blockIdx.x * 256 + threadIdx.x;
    int total = (K >> 4) * (N >> 4) * 32;
    if (idx >= total) return;
    int lane = idx & 31;
    int g = lane >> 2, t = lane & 3;
    int rest = idx >> 5;
    int NP = N >> 4;
    int npair = rest % NP, ks = rest / NP;
    int n0 = npair * 16 + g, k0 = ks * 16 + t * 2;
    uint4 u;
    u.x = f2h2(B[(size_t)k0 * ldb + n0],       B[(size_t)(k0 + 1) * ldb + n0]);
    u.y = f2h2(B[(size_t)(k0 + 8) * ldb + n0], B[(size_t)(k0 + 9) * ldb + n0]);
    u.z = f2h2(B[(size_t)k0 * ldb + n0 + 8],       B[(size_t)(k0 + 1) * ldb + n0 + 8]);
    u.w = f2h2(B[(size_t)(k0 + 8) * ldb + n0 + 8], B[(size_t)(k0 + 9) * ldb + n0 + 8]);
    ((uint4*)Bp)[idx] = u;
}

// Gate-interleaved fp16 B pack for recurrence weights: virtual col
// v = unit*4 + gate <-> source col gate*512 + unit. N = 2048 (NP=128).
// Row k: k < K0 -> W0[k], else W1[k-K0].
__global__ void packB_gatesv_kernel(const float* __restrict__ W0,
                                    const float* __restrict__ W1, int K0,
                                    uint32_t* __restrict__ out, int K, int ldw) {
    int idx = blockIdx.x * 256 + threadIdx.x;
    int total = (K >> 4) * 128 * 32;
    if (idx >= total) return;
    int lane = idx & 31;
    int g = lane >> 2, t = lane & 3;
    int rest = idx >> 5;
    int npair = rest & 127, ks = rest >> 7;
    int n0 = npair * 16 + g, k0 = ks * 16 + t * 2;
#define FETCH(kk, vv) ({                                                     \
        int _u = (vv) >> 2, _g = (vv) & 3;                                   \
        const float* _r = ((kk) < K0) ? (W0 + (size_t)(kk) * ldw)            \
                                      : (W1 + (size_t)((kk) - K0) * ldw);    \
        _r[_g * 512 + _u]; })
    uint4 u;
    u.x = f2h2(FETCH(k0, n0),     FETCH(k0 + 1, n0));
    u.y = f2h2(FETCH(k0 + 8, n0), FETCH(k0 + 9, n0));
    u.z = f2h2(FETCH(k0, n0 + 8),     FETCH(k0 + 1, n0 + 8));
    u.w = f2h2(FETCH(k0 + 8, n0 + 8), FETCH(k0 + 9, n0 + 8));
#undef FETCH
    ((uint4*)out)[idx] = u;
}

// ---------------------------------------------------------------------------
// Packed fp16 mma.sync GEMM with cp.async SMEM ring (4 stages x 8KB).
// Deep async pipeline supplies the ~11KB-in-flight Little's-law requirement
// that the old 2-stage register pipeline (3KB) missed. Fragments stay in
// packed order: stage layout = [A: 256 uint4][B: 256 uint4], LDS.128
// conflict-free by construction. 256 thr = 8 warps (2m x 4n), warp 64x32.
// ---------------------------------------------------------------------------
#define PIPE_S 4

__global__ void __launch_bounds__(256, 2)
mma_gemm_pk(const uint32_t* __restrict__ Ap, const uint32_t* __restrict__ Bp,
            const float* __restrict__ bias, float* __restrict__ C,
            int M, int N, int K, int relu) {
    __shared__ uint32_t smst[PIPE_S * 4096];   // 4 stages x 16KB? -> 4*4096 u32 = 64KB? no: 4096 u32 = 16KB/stage? stage=2048 u32
    // NOTE: stage = 2048 u32 (A 1024 + B 1024) = 8KB; total 4*2048*4 = 32KB.
    int tid = threadIdx.x;
    int wid = tid >> 5, lane = tid & 31;
    int warp_m = wid & 1, warp_n = wid >> 1;
    int g = lane >> 2, t = lane & 3;
    int row0 = blockIdx.x * 128, col0 = blockIdx.y * 128;
    int MS = M >> 4, NP = N >> 4;
    int NC = K >> 4;

    // global fetch bases (uint4 index): 8 contiguous slots x 32 lanes = tid
    const uint4* Asrc = (const uint4*)Ap + (size_t)(row0 >> 4) * 32 + tid;
    const uint4* Bsrc = (const uint4*)Bp + (size_t)(col0 >> 4) * 32 + tid;
    size_t aStep = (size_t)MS * 32;
    size_t bStep = (size_t)NP * 32;

    uint32_t sb = smem_addr_u32(smst);
    uint32_t myA = sb + tid * 16;            // byte addr of this thread's A uint4
    uint32_t myB = sb + 4096 + tid * 16;     // B half of stage 0

    float acc[4][4][4];
#pragma unroll
    for (int i = 0; i < 4; i++)
#pragma unroll
        for (int j = 0; j < 4; j++)
#pragma unroll
            for (int f = 0; f < 4; f++) acc[i][j][f] = 0.f;

    // prologue: issue stages 0..S-2
#pragma unroll
    for (int s = 0; s < PIPE_S - 1; s++) {
        if (s < NC) {
            cpasync16(myA + s * 8192, Asrc + (size_t)s * aStep);
            cpasync16(myB + s * 8192, Bsrc + (size_t)s * bStep);
        }
        CP_COMMIT();
    }

    // fragment smem pointers (uint4 index within a stage)
    const uint4* stA = (const uint4*)smst;   // + stage*512 (uint4)
    int aOff = (warp_m * 4) * 32 + lane;     // + mt*32
    int bOff = 256 + (warp_n * 2) * 32 + lane; // + np*32

    for (int i = 0; i < NC; i++) {
        int nxt = i + PIPE_S - 1;
        int slotNxt = nxt & (PIPE_S - 1);
        if (nxt < NC) {
            cpasync16(myA + slotNxt * 8192, Asrc + (size_t)nxt * aStep);
            cpasync16(myB + slotNxt * 8192, Bsrc + (size_t)nxt * bStep);
        }
        CP_COMMIT();
        CP_WAIT2();
        __syncthreads();

        const uint4* st = stA + (size_t)(i & (PIPE_S - 1)) * 512;
        uint4 aF[4], bF[2];
#pragma unroll
        for (int mt = 0; mt < 4; mt++) aF[mt] = st[aOff + mt * 32];
#pragma unroll
        for (int np = 0; np < 2; np++) bF[np] = st[bOff + np * 32];
#pragma unroll
        for (int mt = 0; mt < 4; mt++) {
            MMA16F(acc[mt][0], aF[mt], bF[0].x, bF[0].y);
            MMA16F(acc[mt][1], aF[mt], bF[0].z, bF[0].w);
            MMA16F(acc[mt][2], aF[mt], bF[1].x, bF[1].y);
            MMA16F(acc[mt][3], aF[mt], bF[1].z, bF[1].w);
        }
        __syncthreads();
    }

    // epilogue (unchanged layout)
#pragma unroll
    for (int mt = 0; mt < 4; mt++) {
        int r = row0 + warp_m * 64 + mt * 16 + g;
#pragma unroll
        for (int j = 0; j < 4; j++) {
            int cc = col0 + warp_n * 32 + j * 8 + t * 2;
            float2 v0, v1;
            v0.x = acc[mt][j][0]; v0.y = acc[mt][j][1];
            v1.x = acc[mt][j][2]; v1.y = acc[mt][j][3];
            if (bias) {
                float b0 = bias[cc], b1 = bias[cc + 1];
                v0.x += b0; v0.y += b1; v1.x += b0; v1.y += b1;
            }
            if (relu) {
                v0.x = fmaxf(v0.x, 0.f); v0.y = fmaxf(v0.y, 0.f);
                v1.x = fmaxf(v1.x, 0.f); v1.y = fmaxf(v1.y, 0.f);
            }
            *(float2*)(C + (size_t)r * N + cc) = v0;
            *(float2*)(C + (size_t)(r + 8) * N + cc) = v1;
        }
    }
}

// ---------------------------------------------------------------------------
// Zero / gather
// ---------------------------------------------------------------------------
__global__ void zero_state_kernel() {
    int i = blockIdx.x * 256 + threadIdx.x;
    if (i < 2*4*NB*NH) ((float*)d_hbuf)[i] = 0.f;
    if (i < 2*4*NB*NH/2) ((uint32_t*)d_hpk)[i] = 0u;
}

__global__ void gather_kernel(const int* __restrict__ src_ids,
                              const int* __restrict__ tgt_ids,
                              const int* __restrict__ rat_ids,
                              const float* __restrict__ src_emb,
                              const float* __restrict__ tgt_emb) {
    int tok = blockIdx.x;          // s*64 + b
    int set = blockIdx.y;          // 0 src, 1 rat, 2 tgt
    int s = tok >> 6, b = tok & 63;
    int id;
    const float* emb;
    float* out;
    if (set == 0)      { id = src_ids[b*NS + s]; emb = src_emb; out = d_src_e; }
    else if (set == 1) { id = rat_ids[b*NS + s]; emb = src_emb; out = d_rat_e; }
    else               { id = tgt_ids[b*NT + s]; emb = tgt_emb; out = d_tgt_e; }
    const float* row = emb + (size_t)id * NE;
    float* dst = out + (size_t)tok * NE;
    for (int e = threadIdx.x; e < NE; e += 256) dst[e] = row[e];
}

// ---------------------------------------------------------------------------
// Persistent encoder: fp16 mma h@Whh. (unchanged from R12)
// ---------------------------------------------------------------------------
__global__ void __launch_bounds__(256)
enc_persistent_kernel() {
    __shared__ float gsm[64][68];
    __shared__ float cs[64][16];
    int blk = blockIdx.x;
    int l = blk >> 5, nt = blk & 31, j0 = nt * 16;
    int tid = threadIdx.x, wid = tid >> 5, lane = tid & 31;
    int warp_m = wid & 3, warp_n = wid >> 2;
    int g = lane >> 2, t = lane & 3;

    for (int p = tid; p < 1024; p += 256) ((float*)cs)[p] = 0.f;
    __syncthreads();

    const uint4* Bpk = (const uint4*)((l & 1) ? d_WhhPkB : d_WhhPkF);
    const uint4* B4 = Bpk + (size_t)(nt * 4 + warp_n * 2) * 32 + lane;
    float* eo = (l < 2) ? d_enc[0] : d_enc[1];
    int half_off = (l & 1) * NH;

    for (int ts = 0; ts < NS; ts++) {
        const uint4* A4 = (const uint4*)d_hpk[ts & 1][l] + warp_m * 32 + lane;
        float acc[4][4];
#pragma unroll
        for (int i = 0; i < 4; i++)
#pragma unroll
            for (int f = 0; f < 4; f++) acc[i][f] = 0.f;

#pragma unroll 4
        for (int ks = 0; ks < 32; ks++) {
            uint4 av = __ldcg(A4 + (size_t)ks * 128);
            uint4 b0 = B4[(size_t)ks * 4096];
            uint4 b1 = B4[(size_t)ks * 4096 + 32];
            MMA16F(acc[0], av, b0.x, b0.y);
            MMA16F(acc[1], av, b0.z, b0.w);
            MMA16F(acc[2], av, b1.x, b1.y);
            MMA16F(acc[3], av, b1.z, b1.w);
        }
#pragma unroll
        for (int j = 0; j < 4; j++) {
            int vloc = warp_n * 32 + j * 8 + t * 2;
            int m = warp_m * 16 + g;
            gsm[m][vloc]     = acc[j][0];
            gsm[m][vloc + 1] = acc[j][1];
            gsm[m + 8][vloc]     = acc[j][2];
            gsm[m + 8][vloc + 1] = acc[j][3];
        }
        __syncthreads();

        int tX = (l & 1) ? (NS - 1 - ts) : ts;
        const float* xw = d_Xw[l] + (size_t)(tX * NB) * H4;
        float* hn = d_hbuf[(ts + 1) & 1][l];
        uint32_t* hp = d_hpk[(ts + 1) & 1][l];
        for (int p = tid; p < 512; p += 256) {
            int m = p >> 3, jp = p & 7;
            int jl0 = jp * 2, jl1 = jl0 + 1;
            int jg0 = j0 + jl0;
            const float* xr = xw + (size_t)m * H4;
            float4 ga = *(const float4*)&gsm[m][jl0 * 4];
            float4 gb = *(const float4*)&gsm[m][jl1 * 4];
            float2 xi = *(const float2*)(xr + jg0);
            float2 xf = *(const float2*)(xr + NH + jg0);
            float2 xg = *(const float2*)(xr + 2 * NH + jg0);
            float2 xo = *(const float2*)(xr + 3 * NH + jg0);
            float cp0 = cs[m][jl0], cp1 = cs[m][jl1];
            float cn0 = sigf(ga.y + xf.x) * cp0 + sigf(ga.x + xi.x) * tanhf(ga.z + xg.x);
            float hv0 = sigf(ga.w + xo.x) * tanhf(cn0);
            float cn1 = sigf(gb.y + xf.y) * cp1 + sigf(gb.x + xi.y) * tanhf(gb.z + xg.y);
            float hv1 = sigf(gb.w + xo.y) * tanhf(cn1);
            cs[m][jl0] = cn0; cs[m][jl1] = cn1;
            *(float2*)(hn + m * NH + jg0) = make_float2(hv0, hv1);
            hp[hpk_idx(m, jg0)] = f2h2(hv0, hv1);
            *(float2*)(eo + ((size_t)m * NS + tX) * H2 + half_off + jg0) =
                make_float2(hv0, hv1);
        }
        grid_bar();
    }
    if (l == 0) {
        for (int p = tid; p < 1024; p += 256) {
            int m = p >> 4, jj = p & 15;
            d_cfin[m * NH + j0 + jj] = cs[m][jj];
        }
    }
}

// ---------------------------------------------------------------------------
// Persistent decoder: 4 phases/step; phase 3 on fp16 mma. (unchanged from R12)
// ---------------------------------------------------------------------------
__global__ void __launch_bounds__(256)
dec_persistent_kernel(const float* __restrict__ att_W1,
                      const float* __restrict__ att_W2,
                      const float* __restrict__ att_b2) {
    __shared__ float As[16][64];
    __shared__ float Bq[16][17];
    __shared__ float gsm[64][68];
    __shared__ float qs[H3];
    __shared__ float w2s[H3];
    __shared__ float logits[NS];
    __shared__ float wts[NS];
    __shared__ float sred[2];

    int blk = blockIdx.x, tid = threadIdx.x;
    int tx = tid & 15, ty = tid >> 4;
    int aRow = tid >> 2, aCol = (tid & 3) * 4;
    int wid = tid >> 5, lane = tid & 31;
    int warp_m = wid & 3, warp_n = wid >> 2;
    int g = lane >> 2, lt = lane & 3;

    int p = blk * 256 + tid;           // 0..32767
    int pm = p >> 8, pjp = p & 255, pj0 = pjp * 2;
    float c0 = 0.f, c1 = 0.f;
    if (p < 16384) {
        c0 = d_cfin[pm * NH + pj0];
        c1 = d_cfin[pm * NH + pj0 + 1];
        const float* h0 = d_hbuf[0][0];
        d_xpk[hpk_idx(pm, 2048 + pj0)] =
            f2h2(h0[pm * NH + pj0], h0[pm * NH + pj0 + 1]);
    }

    for (int t = 0; t < NSTEPS; t++) {
        const float* h = (t == 0) ? d_hbuf[0][0] : d_hdec[t & 1];

        // ---- Phase 1: q[64,1536] = h[64,512] @ W1[1024:1536, :]  (fp32)
        if (blk < 96) {
            int c0q = blk * 16;
            float acc[4] = {0.f, 0.f, 0.f, 0.f};
            for (int kb = 0; kb < NH; kb += 16) {
                float4 va = __ldcg((const float4*)(h + aRow * NH + kb + aCol));
                As[aCol+0][aRow] = va.x; As[aCol+1][aRow] = va.y;
                As[aCol+2][aRow] = va.z; As[aCol+3][aRow] = va.w;
                Bq[tid >> 4][tid & 15] =
                    att_W1[(size_t)(H2 + kb + (tid >> 4)) * H3 + c0q + (tid & 15)];
                __syncthreads();
#pragma unroll
                for (int k = 0; k < 16; k++) {
                    float b = Bq[k][tx];
#pragma unroll
                    for (int i = 0; i < 4; i++)
                        acc[i] = fmaf(As[k][ty*4 + i], b, acc[i]);
                }
                __syncthreads();
            }
#pragma unroll
            for (int i = 0; i < 4; i++)
                d_q[(ty*4 + i) * H3 + c0q + tx] = acc[i];
        }
        grid_bar();

        // ---- Phase 2: attention (both encoders); writes A fp32 + packed fp16
        {
            int b = blk & 63, e = blk >> 6;
            const float* P   = d_P[e] + (size_t)(b * NS) * H3;
            const float* enc = d_enc[e] + (size_t)(b * NS) * H2;
            for (int j2 = tid; j2 < H3; j2 += 256) {
                qs[j2]  = __ldcg(&d_q[b * H3 + j2]);
                w2s[j2] = att_W2[j2];
            }
            __syncthreads();
            int w = tid >> 5, ln = tid & 31;
            float b2v = att_b2[0];
#pragma unroll
            for (int si = 0; si < 8; si++) {
                int s = w * 8 + si;
                const float* Pr = P + (size_t)s * H3;
                float part = 0.f;
                for (int j2 = ln; j2 < H3; j2 += 32)
                    part += fmaxf(Pr[j2] + qs[j2], 0.f) * w2s[j2];
#pragma unroll
                for (int off = 16; off; off >>= 1)
                    part += __shfl_down_sync(0xffffffffu, part, off);
                if (ln == 0) logits[s] = part + b2v;
            }
            __syncthreads();
            if (tid == 0) {
                float mx = -1e30f;
                for (int s = 0; s < NS; s++) mx = fmaxf(mx, logits[s]);
                sred[0] = mx;
            }
            __syncthreads();
            if (tid < NS) wts[tid] = expf(logits[tid] - sred[0]);
            __syncthreads();
            if (tid == 0) {
                float sm = 0.f;
                for (int s = 0; s < NS; s++) sm += wts[s];
                sred[1] = 1.f / sm;
            }
            __syncthreads();
            float inv = sred[1];
            float* outA = d_Abuf[e] + (size_t)(t * NB + b) * H2;
            for (int chp = tid; chp < 512; chp += 256) {
                int ch = chp * 2;
                float a0 = 0.f, a1 = 0.f;
                const float* ebase = enc + ch;
                for (int s = 0; s < NS; s++) {
                    float2 ev = *(const float2*)(ebase + (size_t)s * H2);
                    float wv = wts[s];
                    a0 += wv * ev.x; a1 += wv * ev.y;
                }
                a0 *= inv; a1 *= inv;
                *(float2*)(outA + ch) = make_float2(a0, a1);
                d_xpk[hpk_idx(b, e * 1024 + ch)] = f2h2(a0, a1);
            }
        }
        grid_bar();

        // ---- Phase 3 (fp16 mma): [A,Ar,h](K=2560 packed) @ WdecPk, K-split x4
        {
            int ksp = blk >> 5, nt2 = blk & 31;
            int j0v = nt2 * 16;
            const uint4* A4 = (const uint4*)d_xpk + warp_m * 32 + lane;
            const uint4* B4 = (const uint4*)d_WdecPk +
                              (size_t)(nt2 * 4 + warp_n * 2) * 32 + lane;
            float acc[4][4];
#pragma unroll
            for (int i = 0; i < 4; i++)
#pragma unroll
                for (int f = 0; f < 4; f++) acc[i][f] = 0.f;

            int k0 = ksp * 40;
#pragma unroll 4
            for (int ks = k0; ks < k0 + 40; ks++) {
                uint4 av = __ldcg(A4 + (size_t)ks * 128);
                uint4 b0 = B4[(size_t)ks * 4096];
                uint4 b1 = B4[(size_t)ks * 4096 + 32];
                MMA16F(acc[0], av, b0.x, b0.y);
                MMA16F(acc[1], av, b0.z, b0.w);
                MMA16F(acc[2], av, b1.x, b1.y);
                MMA16F(acc[3], av, b1.z, b1.w);
            }
#pragma unroll
            for (int j = 0; j < 4; j++) {
                int vloc = warp_n * 32 + j * 8 + lt * 2;
                int m = warp_m * 16 + g;
                gsm[m][vloc]     = acc[j][0];
                gsm[m][vloc + 1] = acc[j][1];
                gsm[m + 8][vloc]     = acc[j][2];
                gsm[m + 8][vloc + 1] = acc[j][3];
            }
            __syncthreads();
            float* gp = d_gpart + (size_t)(ksp * NB) * H4;
            for (int pp = tid; pp < 1024; pp += 256) {
                int m = pp >> 4, jj = pp & 15;
                float4 gv = *(const float4*)&gsm[m][jj * 4];
                *(float4*)(gp + (size_t)m * H4 + (j0v + jj) * 4) = gv;
            }
            __syncthreads();   // gsm reused next step
        }
        grid_bar();

        // ---- Phase 4: gates; threads p<16384 own unit pairs (v-layout partials)
        if (p < 16384) {
            const float* xr = d_tgtW + (size_t)(t * NB + pm) * H4;
            float4 sa = make_float4(0.f, 0.f, 0.f, 0.f);
            float4 sb = make_float4(0.f, 0.f, 0.f, 0.f);
#pragma unroll
            for (int ks = 0; ks < 4; ks++) {
                const float* gpb = d_gpart + (size_t)(ks * NB + pm) * H4 + pj0 * 4;
                float4 va = __ldcg((const float4*)gpb);
                float4 vb = __ldcg((const float4*)(gpb + 4));
                sa.x += va.x; sa.y += va.y; sa.z += va.z; sa.w += va.w;
                sb.x += vb.x; sb.y += vb.y; sb.z += vb.z; sb.w += vb.w;
            }
            float2 xi = *(const float2*)(xr + pj0);
            float2 xf = *(const float2*)(xr + NH + pj0);
            float2 xg = *(const float2*)(xr + 2 * NH + pj0);
            float2 xo = *(const float2*)(xr + 3 * NH + pj0);
            float cn0 = sigf(sa.y + xf.x) * c0 + sigf(sa.x + xi.x) * tanhf(sa.z + xg.x);
            float hv0 = sigf(sa.w + xo.x) * tanhf(cn0);
            float cn1 = sigf(sb.y + xf.y) * c1 + sigf(sb.x + xi.y) * tanhf(sb.z + xg.y);
            float hv1 = sigf(sb.w + xo.y) * tanhf(cn1);
            c0 = cn0; c1 = cn1;
            *(float2*)(d_hdec[(t + 1) & 1] + pm * NH + pj0) = make_float2(hv0, hv1);
            *(float2*)(d_Dbuf + ((size_t)t * NB + pm) * NH + pj0) = make_float2(hv0, hv1);
            d_xpk[hpk_idx(pm, 2048 + pj0)] = f2h2(hv0, hv1);
        }
        grid_bar();
    }
}

// ---------------------------------------------------------------------------
// Assemble classifier input ci[r=b*T+t] = [tgt_e, A, Ar, g, D] (zeros past STEPS)
// ---------------------------------------------------------------------------
__global__ void assemble_kernel(const float* __restrict__ graph_embs) {
    int r = blockIdx.x;
    int b = r >> 6, t = r & 63;
    float* row = d_ci + (size_t)r * CIW;
    bool live = (t < NSTEPS);
    for (int c = threadIdx.x; c < CIW; c += 256) {
        float v;
        if (c < 512)       v = d_tgt_e[((size_t)t * NB + b) * NE + c];
        else if (c < 1536) v = live ? d_Abuf[0][((size_t)t * NB + b) * H2 + (c - 512)]  : 0.f;
        else if (c < 2560) v = live ? d_Abuf[1][((size_t)t * NB + b) * H2 + (c - 1536)] : 0.f;
        else if (c < 2816) v = graph_embs[b * NG + (c - 2560)];
        else               v = live ? d_Dbuf[((size_t)t * NB + b) * NH + (c - 2816)]    : 0.f;
        row[c] = v;
    }
}

// ---------------------------------------------------------------------------
// Host launch
// ---------------------------------------------------------------------------
static float* symaddr(const void* s) {
    void* p = nullptr;
    cudaGetSymbolAddress(&p, s);
    return (float*)p;
}

static void packA(const float* A, uint32_t* Ap, int M, int K, int lda) {
    int total = (K >> 4) * (M >> 4) * 32;
    packA_kernel<<<(total + 255) / 256, 256>>>(A, Ap, M, K, lda);
}
static void packB(const float* B, uint32_t* Bp, int K, int N, int ldb) {
    int total = (K >> 4) * (N >> 4) * 32;
    packB_kernel<<<(total + 255) / 256, 256>>>(B, Bp, K, N, ldb);
}
static void gemm_pk(const uint32_t* Ap, const uint32_t* Bp, const float* bias,
                    float* C, int M, int N, int K, int relu) {
    dim3 g(M / 128, N / 128);   // x = M tiles (adjacent CTAs share the B band)
    mma_gemm_pk<<<g, 256>>>(Ap, Bp, bias, C, M, N, K, relu);
}

extern "C" void kernel_launch(void* const* d_in, const int* in_sizes, int n_in,
                              void* d_out, int out_size) {
    const int*   source_data = (const int*)d_in[0];
    const int*   target_data = (const int*)d_in[1];
    const int*   rationales  = (const int*)d_in[2];
    const float* graph_embs  = (const float*)d_in[3];
    const float* src_emb     = (const float*)d_in[4];
    const float* tgt_emb     = (const float*)d_in[5];
    const float* enc_Wih_f   = (const float*)d_in[6];
    const float* enc_Whh_f   = (const float*)d_in[7];
    const float* enc_b_f     = (const float*)d_in[8];
    const float* enc_Wih_b   = (const float*)d_in[9];
    const float* enc_Whh_b   = (const float*)d_in[10];
    const float* enc_b_b     = (const float*)d_in[11];
    const float* dec_Wih     = (const float*)d_in[12];
    const float* dec_Whh     = (const float*)d_in[13];
    const float* dec_b       = (const float*)d_in[14];
    const float* att_W1      = (const float*)d_in[15];
    const float* att_b1      = (const float*)d_in[16];
    const float* att_W2      = (const float*)d_in[17];
    const float* att_b2      = (const float*)d_in[18];
    const float* cls_Wg      = (const float*)d_in[19];
    const float* cls_bg      = (const float*)d_in[20];
    const float* cls_W2      = (const float*)d_in[21];
    const float* cls_b2      = (const float*)d_in[22];
    float* out = (float*)d_out;

    float* p_src_e = symaddr(d_src_e);
    float* p_rat_e = symaddr(d_rat_e);
    float* p_tgt_e = symaddr(d_tgt_e);
    float* p_Xw    = symaddr(d_Xw);
    float* p_enc   = symaddr(d_enc);
    float* p_P     = symaddr(d_P);
    float* p_tgtW  = symaddr(d_tgtW);
    float* p_ci    = symaddr(d_ci);
    float* p_hid   = symaddr(d_hid);
    uint32_t* p_Ap = (uint32_t*)symaddr(d_Ap);
    uint32_t* p_Bp = (uint32_t*)symaddr(d_Bp);
    uint32_t* p_WhhF = (uint32_t*)symaddr(d_WhhPkF);
    uint32_t* p_WhhB = (uint32_t*)symaddr(d_WhhPkB);
    uint32_t* p_Wdec = (uint32_t*)symaddr(d_WdecPk);
    void*  p_bar   = nullptr;
    cudaGetSymbolAddress(&p_bar, g_bar);

    const size_t XW  = (size_t)NS * NB * H4;
    const size_t ENC = (size_t)NB * NS * H2;
    const size_t PP  = (size_t)NB * NS * H3;

    cudaMemsetAsync(p_bar, 0, sizeof(unsigned int));
    zero_state_kernel<<<1024, 256>>>();
    gather_kernel<<<dim3(4096, 3), 256>>>(source_data, target_data, rationales,
                                          src_emb, tgt_emb);

    // gate-v-interleaved packed recurrence weights (fp16)
    packB_gatesv_kernel<<<512, 256>>>(enc_Whh_f, enc_Whh_f, NH, p_WhhF, NH, H4);
    packB_gatesv_kernel<<<512, 256>>>(enc_Whh_b, enc_Whh_b, NH, p_WhhB, NH, H4);
    packB_gatesv_kernel<<<2560, 256>>>(dec_Wih + (size_t)NE * H4, dec_Whh, 2048,
                                       p_Wdec, 2560, H4);

    // x @ Wih + b, hoisted for all 4 encoder LSTMs (packed fp16 mma)
    packA(p_src_e, p_Ap,            4096, NE, NE);
    packA(p_rat_e, p_Ap + AP_SLOT1, 4096, NE, NE);
    packB(enc_Wih_f, p_Bp, NE, H4, H4);
    gemm_pk(p_Ap,            p_Bp, enc_b_f, p_Xw + 0*XW, 4096, H4, NE, 0);
    gemm_pk(p_Ap + AP_SLOT1, p_Bp, enc_b_f, p_Xw + 2*XW, 4096, H4, NE, 0);
    packB(enc_Wih_b, p_Bp, NE, H4, H4);
    gemm_pk(p_Ap,            p_Bp, enc_b_b, p_Xw + 1*XW, 4096, H4, NE, 0);
    gemm_pk(p_Ap + AP_SLOT1, p_Bp, enc_b_b, p_Xw + 3*XW, 4096, H4, NE, 0);

    // tgt_e @ dec_Wih[:E] + dec_b, hoisted for all 32 decoder steps
    packA(p_tgt_e, p_Ap, NSTEPS * NB, NE, NE);
    packB(dec_Wih, p_Bp, NE, H4, H4);           // first E rows
    gemm_pk(p_Ap, p_Bp, dec_b, p_tgtW, NSTEPS * NB, H4, NE, 0);

    // encoder recurrence: persistent, fp16 tensor-core
    enc_persistent_kernel<<<GRID_PERS, 256>>>();

    // attention pre-projection: enc_out @ W1[:2H] + b1
    packA(p_enc + 0*ENC, p_Ap,            4096, H2, H2);
    packA(p_enc + 1*ENC, p_Ap + AP_SLOT1, 4096, H2, H2);
    packB(att_W1, p_Bp, H2, H3, H3);            // first 2H rows
    gemm_pk(p_Ap,            p_Bp, att_b1, p_P + 0*PP, 4096, H3, H2, 0);
    gemm_pk(p_Ap + AP_SLOT1, p_Bp, att_b1, p_P + 1*PP, 4096, H3, H2, 0);

    // decoder recurrence: persistent, fp16 tensor-core phase 3
    dec_persistent_kernel<<<GRID_PERS, 256>>>(att_W1, att_W2, att_b2);

    // classifier
    assemble_kernel<<<4096, 256>>>(graph_embs);
    packA(p_ci, p_Ap, 4096, CIW, CIW);
    packB(cls_Wg, p_Bp, CIW, H2, H2);
    gemm_pk(p_Ap, p_Bp, cls_bg, p_hid, 4096, H2, CIW, 1);
    packA(p_hid, p_Ap, 4096, H2, H2);
    packB(cls_W2, p_Bp, H2, NV, NV);
    gemm_pk(p_Ap, p_Bp, cls_b2, out, 4096, NV, H2, 0);
}

// round 14
// speedup vs baseline: 1.0490x; 1.0490x over previous
#include <cuda_runtime.h>
#include <cuda_fp16.h>
#include <math.h>
#include <stdint.h>

// ---------------------------------------------------------------------------
// Problem constants: B=64, S=64, T=64, STEPS=32, E=512, H=512, G=256, V=32000
// ---------------------------------------------------------------------------
#define NB   64
#define NS   64
#define NT   64
#define NSTEPS 32
#define NE   512
#define NH   512
#define NG   256
#define NV   32000
#define H4   2048
#define H2   1024
#define H3   1536
#define CIW  3328   // E + 2H + 2H + G + H

#define GRID_PERS 128   // persistent-kernel grid (<=148 SMs -> co-resident)

// ---------------------------------------------------------------------------
// Scratch (device globals; no allocations allowed)
// ---------------------------------------------------------------------------
__device__ float d_src_e[NS*NB*NE];        // time-major [s][b][e]
__device__ float d_rat_e[NS*NB*NE];
__device__ float d_tgt_e[NT*NB*NE];        // [t][b][e]
__device__ float d_Xw[4][NS*NB*H4];        // x@Wih + b per lstm {srcF,srcB,ratF,ratB}
__device__ float d_hbuf[2][4][NB*NH];      // ping-pong h (encoder, fp32)
__device__ float d_enc[2][NB*NS*H2];       // [b][s][2H]; 0=src 1=rat
__device__ float d_P[2][NB*NS*H3];         // enc_out @ W1[:2H] + b1
__device__ float d_q[NB*H3];               // h @ W1[2H:]
__device__ float d_Abuf[2][NSTEPS*NB*H2];  // attention outputs A, Ar
__device__ float d_Dbuf[NSTEPS*NB*NH];     // decoder h per step
__device__ float d_tgtW[NSTEPS*NB*H4];     // tgt_e @ dec_Wih[:E] + dec_b
__device__ float d_hdec[2][NB*NH];
__device__ float d_cfin[NB*NH];            // encoder (src,fwd) final c
__device__ float d_gpart[4*NB*H4];         // decoder gemm partials (v-layout)
__device__ float d_ci[(size_t)NB*NT*CIW];
__device__ float d_hid[(size_t)NB*NT*H2];
// fragment-packed fp16 operand scratch (uint32 = half2)
__device__ uint32_t d_Ap[8*1024*1024];     // 32MB: slot0 @0, slot1 @4M
__device__ uint32_t d_Bp[(size_t)H2*NV/2]; // 65MB (max = cls_W2 in half2)
// recurrence tensor-core operands (packed fp16)
__device__ uint32_t d_hpk[2][4][NB*NH/2];  // encoder h, ping-pong, per lstm
__device__ uint32_t d_xpk[NB*2560/2];      // decoder [A,Ar,h] K=2560
__device__ uint32_t d_WhhPkF[NH*H4/2];     // gate-v-interleaved enc Whh fwd (2MB)
__device__ uint32_t d_WhhPkB[NH*H4/2];     // bwd
__device__ uint32_t d_WdecPk[2560*H4/2];   // [dec_Wih[512:]; dec_Whh] (10MB)
__device__ unsigned int g_bar = 0;

#define AP_SLOT1 (4u*1024u*1024u)

__device__ __forceinline__ float sigf(float x) { return 1.f / (1.f + expf(-x)); }

// Software grid barrier. All GRID_PERS blocks must be co-resident.
__device__ __forceinline__ void grid_bar() {
    __syncthreads();
    if (threadIdx.x == 0) {
        __threadfence();                       // release
        unsigned int t = atomicAdd(&g_bar, 1u);
        unsigned int target = t - (t & (GRID_PERS - 1u)) + GRID_PERS;
        unsigned int v;
        do {
            asm volatile("ld.acquire.gpu.global.u32 %0, [%1];"
                         : "=r"(v) : "l"(&g_bar) : "memory");
        } while (v < target);
    }
    __syncthreads();
}

__device__ __forceinline__ uint32_t f2h2(float lo, float hi) {
    __half2 h = __floats2half2_rn(lo, hi);
    return *reinterpret_cast<uint32_t*>(&h);
}

// u32 index inside a packed-A fp16 buffer with MS=4 m-slots (M=64), for the
// half2 holding elements (m, j) and (m, j+1); j must be even.
__device__ __forceinline__ uint32_t hpk_idx(int m, int j) {
    int ks = j >> 4;
    int t = (j >> 1) & 3;
    int khi = (j >> 3) & 1;
    int g = m & 7;
    int mhi = (m >> 3) & 1;
    int mslot = m >> 4;
    return (uint32_t)((((ks * 4 + mslot) * 32 + g * 4 + t) << 2) + mhi + (khi << 1));
}

#define MMA16F(accv, av, b0, b1)                                              \
    asm volatile(                                                             \
        "mma.sync.aligned.m16n8k16.row.col.f32.f16.f16.f32 "                  \
        "{%0,%1,%2,%3}, {%4,%5,%6,%7}, {%8,%9}, {%0,%1,%2,%3};"               \
        : "+f"((accv)[0]), "+f"((accv)[1]), "+f"((accv)[2]), "+f"((accv)[3])  \
        : "r"((av).x), "r"((av).y), "r"((av).z), "r"((av).w),                 \
          "r"(b0), "r"(b1))

// ---------------------------------------------------------------------------
// Coalesced smem-staged pack kernels (same output layout as before).
// packA_fast: grid (M/64, K/16). Loads a [64m x 16k] fp32 tile with float4
// row reads, emits 4 m-slots x 32 lanes of packed uint4.
// ---------------------------------------------------------------------------
__global__ void packA_fast_kernel(const float* __restrict__ A,
                                  uint32_t* __restrict__ Ap,
                                  int M, int K, int lda) {
    __shared__ float sm[64][20];
    int mb = blockIdx.x, ks = blockIdx.y;
    int tid = threadIdx.x;
    int MS = M >> 4;
    {
        int r = tid >> 2, c4 = (tid & 3) * 4;
        float4 v = *(const float4*)(A + (size_t)(mb * 64 + r) * lda + ks * 16 + c4);
        sm[r][c4] = v.x; sm[r][c4 + 1] = v.y; sm[r][c4 + 2] = v.z; sm[r][c4 + 3] = v.w;
    }
    __syncthreads();
    if (tid < 128) {
        int msl = tid >> 5, lane = tid & 31;
        int g = lane >> 2, t = lane & 3;
        int m = msl * 16 + g, k = t * 2;
        uint4 u;
        u.x = f2h2(sm[m][k],         sm[m][k + 1]);
        u.y = f2h2(sm[m + 8][k],     sm[m + 8][k + 1]);
        u.z = f2h2(sm[m][k + 8],     sm[m][k + 9]);
        u.w = f2h2(sm[m + 8][k + 8], sm[m + 8][k + 9]);
        ((uint4*)Ap)[((size_t)ks * MS + (mb * 4 + msl)) * 32 + lane] = u;
    }
}

// packB_fast: grid (K/16, N/256). Loads a [16k x 256n] fp32 tile with float4
// row reads, emits 16 npairs x 32 lanes of packed uint4.
__global__ void packB_fast_kernel(const float* __restrict__ B,
                                  uint32_t* __restrict__ Bp,
                                  int K, int N, int ldb) {
    __shared__ float sm[16][260];
    int ks = blockIdx.x, nb = blockIdx.y;
    int tid = threadIdx.x;
    int NP = N >> 4;
    int k0 = ks * 16, n0 = nb * 256;
#pragma unroll
    for (int i = 0; i < 4; i++) {
        int idx = tid + i * 256;
        int r = idx >> 6, c4 = (idx & 63) * 4;
        float4 v = *(const float4*)(B + (size_t)(k0 + r) * ldb + n0 + c4);
        sm[r][c4] = v.x; sm[r][c4 + 1] = v.y; sm[r][c4 + 2] = v.z; sm[r][c4 + 3] = v.w;
    }
    __syncthreads();
#pragma unroll
    for (int i = 0; i < 2; i++) {
        int idx = tid + i * 256;
        int np = idx >> 5, lane = idx & 31;
        int g = lane >> 2, t = lane & 3;
        int nn = np * 16 + g, kk = t * 2;
        uint4 u;
        u.x = f2h2(sm[kk][nn],         sm[kk + 1][nn]);
        u.y = f2h2(sm[kk + 8][nn],     sm[kk + 9][nn]);
        u.z = f2h2(sm[kk][nn + 8],     sm[kk + 1][nn + 8]);
        u.w = f2h2(sm[kk + 8][nn + 8], sm[kk + 9][nn + 8]);
        ((uint4*)Bp)[((size_t)ks * NP + (nb * 16 + np)) * 32 + lane] = u;
    }
}

// Gate-interleaved fp16 B pack for recurrence weights: virtual col
// v = unit*4 + gate <-> source col gate*512 + unit. N = 2048 (NP=128).
// Row k: k < K0 -> W0[k], else W1[k-K0].
__global__ void packB_gatesv_kernel(const float* __restrict__ W0,
                                    const float* __restrict__ W1, int K0,
                                    uint32_t* __restrict__ out, int K, int ldw) {
    int idx = blockIdx.x * 256 + threadIdx.x;
    int total = (K >> 4) * 128 * 32;
    if (idx >= total) return;
    int lane = idx & 31;
    int g = lane >> 2, t = lane & 3;
    int rest = idx >> 5;
    int npair = rest & 127, ks = rest >> 7;
    int n0 = npair * 16 + g, k0 = ks * 16 + t * 2;
#define FETCH(kk, vv) ({                                                     \
        int _u = (vv) >> 2, _g = (vv) & 3;                                   \
        const float* _r = ((kk) < K0) ? (W0 + (size_t)(kk) * ldw)            \
                                      : (W1 + (size_t)((kk) - K0) * ldw);    \
        _r[_g * 512 + _u]; })
    uint4 u;
    u.x = f2h2(FETCH(k0, n0),     FETCH(k0 + 1, n0));
    u.y = f2h2(FETCH(k0 + 8, n0), FETCH(k0 + 9, n0));
    u.z = f2h2(FETCH(k0, n0 + 8),     FETCH(k0 + 1, n0 + 8));
    u.w = f2h2(FETCH(k0 + 8, n0 + 8), FETCH(k0 + 9, n0 + 8));
#undef FETCH
    ((uint4*)out)[idx] = u;
}

// ---------------------------------------------------------------------------
// Packed fp16 mma.sync GEMM (R12 register-pipeline version - known good)
// ---------------------------------------------------------------------------
__global__ void __launch_bounds__(256, 2)
mma_gemm_pk(const uint32_t* __restrict__ Ap, const uint32_t* __restrict__ Bp,
            const float* __restrict__ bias, float* __restrict__ C,
            int M, int N, int K, int relu) {
    int tid = threadIdx.x;
    int wid = tid >> 5, lane = tid & 31;
    int warp_m = wid & 1, warp_n = wid >> 1;
    int g = lane >> 2, t = lane & 3;
    int row0 = blockIdx.x * 128, col0 = blockIdx.y * 128;
    int MS = M >> 4, NP = N >> 4;
    int KS = K >> 4;

    const uint4* A4 = (const uint4*)Ap + (size_t)((row0 >> 4) + warp_m * 4) * 32 + lane;
    const uint4* B4 = (const uint4*)Bp + (size_t)((col0 >> 4) + warp_n * 2) * 32 + lane;
    size_t aStep = (size_t)MS * 32;
    size_t bStep = (size_t)NP * 32;

    float acc[4][4][4];
#pragma unroll
    for (int i = 0; i < 4; i++)
#pragma unroll
        for (int j = 0; j < 4; j++)
#pragma unroll
            for (int f = 0; f < 4; f++) acc[i][j][f] = 0.f;

    uint4 pa0[4], pb0[2], pa1[4], pb1[2];
#pragma unroll
    for (int mt = 0; mt < 4; mt++) pa0[mt] = A4[mt * 32];
#pragma unroll
    for (int np = 0; np < 2; np++) pb0[np] = B4[np * 32];

    for (int ks = 0; ks < KS; ks += 2) {
        {
            const uint4* An = A4 + (size_t)(ks + 1) * aStep;
            const uint4* Bn = B4 + (size_t)(ks + 1) * bStep;
#pragma unroll
            for (int mt = 0; mt < 4; mt++) pa1[mt] = An[mt * 32];
#pragma unroll
            for (int np = 0; np < 2; np++) pb1[np] = Bn[np * 32];
        }
#pragma unroll
        for (int mt = 0; mt < 4; mt++) {
            MMA16F(acc[mt][0], pa0[mt], pb0[0].x, pb0[0].y);
            MMA16F(acc[mt][1], pa0[mt], pb0[0].z, pb0[0].w);
            MMA16F(acc[mt][2], pa0[mt], pb0[1].x, pb0[1].y);
            MMA16F(acc[mt][3], pa0[mt], pb0[1].z, pb0[1].w);
        }
        if (ks + 2 < KS) {
            const uint4* An = A4 + (size_t)(ks + 2) * aStep;
            const uint4* Bn = B4 + (size_t)(ks + 2) * bStep;
#pragma unroll
            for (int mt = 0; mt < 4; mt++) pa0[mt] = An[mt * 32];
#pragma unroll
            for (int np = 0; np < 2; np++) pb0[np] = Bn[np * 32];
        }
#pragma unroll
        for (int mt = 0; mt < 4; mt++) {
            MMA16F(acc[mt][0], pa1[mt], pb1[0].x, pb1[0].y);
            MMA16F(acc[mt][1], pa1[mt], pb1[0].z, pb1[0].w);
            MMA16F(acc[mt][2], pa1[mt], pb1[1].x, pb1[1].y);
            MMA16F(acc[mt][3], pa1[mt], pb1[1].z, pb1[1].w);
        }
    }

#pragma unroll
    for (int mt = 0; mt < 4; mt++) {
        int r = row0 + warp_m * 64 + mt * 16 + g;
#pragma unroll
        for (int j = 0; j < 4; j++) {
            int cc = col0 + warp_n * 32 + j * 8 + t * 2;
            float2 v0, v1;
            v0.x = acc[mt][j][0]; v0.y = acc[mt][j][1];
            v1.x = acc[mt][j][2]; v1.y = acc[mt][j][3];
            if (bias) {
                float b0 = bias[cc], b1 = bias[cc + 1];
                v0.x += b0; v0.y += b1; v1.x += b0; v1.y += b1;
            }
            if (relu) {
                v0.x = fmaxf(v0.x, 0.f); v0.y = fmaxf(v0.y, 0.f);
                v1.x = fmaxf(v1.x, 0.f); v1.y = fmaxf(v1.y, 0.f);
            }
            *(float2*)(C + (size_t)r * N + cc) = v0;
            *(float2*)(C + (size_t)(r + 8) * N + cc) = v1;
        }
    }
}

// ---------------------------------------------------------------------------
// Zero / gather
// ---------------------------------------------------------------------------
__global__ void zero_state_kernel() {
    int i = blockIdx.x * 256 + threadIdx.x;
    if (i < 2*4*NB*NH) ((float*)d_hbuf)[i] = 0.f;
    if (i < 2*4*NB*NH/2) ((uint32_t*)d_hpk)[i] = 0u;
}

__global__ void gather_kernel(const int* __restrict__ src_ids,
                              const int* __restrict__ tgt_ids,
                              const int* __restrict__ rat_ids,
                              const float* __restrict__ src_emb,
                              const float* __restrict__ tgt_emb) {
    int tok = blockIdx.x;          // s*64 + b
    int set = blockIdx.y;          // 0 src, 1 rat, 2 tgt
    int s = tok >> 6, b = tok & 63;
    int id;
    const float* emb;
    float* out;
    if (set == 0)      { id = src_ids[b*NS + s]; emb = src_emb; out = d_src_e; }
    else if (set == 1) { id = rat_ids[b*NS + s]; emb = src_emb; out = d_rat_e; }
    else               { id = tgt_ids[b*NT + s]; emb = tgt_emb; out = d_tgt_e; }
    const float* row = emb + (size_t)id * NE;
    float* dst = out + (size_t)tok * NE;
    for (int e = threadIdx.x; e < NE; e += 256) dst[e] = row[e];
}

// ---------------------------------------------------------------------------
// Persistent encoder: fp16 mma h@Whh. (unchanged from R12)
// ---------------------------------------------------------------------------
__global__ void __launch_bounds__(256)
enc_persistent_kernel() {
    __shared__ float gsm[64][68];
    __shared__ float cs[64][16];
    int blk = blockIdx.x;
    int l = blk >> 5, nt = blk & 31, j0 = nt * 16;
    int tid = threadIdx.x, wid = tid >> 5, lane = tid & 31;
    int warp_m = wid & 3, warp_n = wid >> 2;
    int g = lane >> 2, t = lane & 3;

    for (int p = tid; p < 1024; p += 256) ((float*)cs)[p] = 0.f;
    __syncthreads();

    const uint4* Bpk = (const uint4*)((l & 1) ? d_WhhPkB : d_WhhPkF);
    const uint4* B4 = Bpk + (size_t)(nt * 4 + warp_n * 2) * 32 + lane;
    float* eo = (l < 2) ? d_enc[0] : d_enc[1];
    int half_off = (l & 1) * NH;

    for (int ts = 0; ts < NS; ts++) {
        const uint4* A4 = (const uint4*)d_hpk[ts & 1][l] + warp_m * 32 + lane;
        float acc[4][4];
#pragma unroll
        for (int i = 0; i < 4; i++)
#pragma unroll
            for (int f = 0; f < 4; f++) acc[i][f] = 0.f;

#pragma unroll 4
        for (int ks = 0; ks < 32; ks++) {
            uint4 av = __ldcg(A4 + (size_t)ks * 128);
            uint4 b0 = B4[(size_t)ks * 4096];
            uint4 b1 = B4[(size_t)ks * 4096 + 32];
            MMA16F(acc[0], av, b0.x, b0.y);
            MMA16F(acc[1], av, b0.z, b0.w);
            MMA16F(acc[2], av, b1.x, b1.y);
            MMA16F(acc[3], av, b1.z, b1.w);
        }
#pragma unroll
        for (int j = 0; j < 4; j++) {
            int vloc = warp_n * 32 + j * 8 + t * 2;
            int m = warp_m * 16 + g;
            gsm[m][vloc]     = acc[j][0];
            gsm[m][vloc + 1] = acc[j][1];
            gsm[m + 8][vloc]     = acc[j][2];
            gsm[m + 8][vloc + 1] = acc[j][3];
        }
        __syncthreads();

        int tX = (l & 1) ? (NS - 1 - ts) : ts;
        const float* xw = d_Xw[l] + (size_t)(tX * NB) * H4;
        float* hn = d_hbuf[(ts + 1) & 1][l];
        uint32_t* hp = d_hpk[(ts + 1) & 1][l];
        for (int p = tid; p < 512; p += 256) {
            int m = p >> 3, jp = p & 7;
            int jl0 = jp * 2, jl1 = jl0 + 1;
            int jg0 = j0 + jl0;
            const float* xr = xw + (size_t)m * H4;
            float4 ga = *(const float4*)&gsm[m][jl0 * 4];
            float4 gb = *(const float4*)&gsm[m][jl1 * 4];
            float2 xi = *(const float2*)(xr + jg0);
            float2 xf = *(const float2*)(xr + NH + jg0);
            float2 xg = *(const float2*)(xr + 2 * NH + jg0);
            float2 xo = *(const float2*)(xr + 3 * NH + jg0);
            float cp0 = cs[m][jl0], cp1 = cs[m][jl1];
            float cn0 = sigf(ga.y + xf.x) * cp0 + sigf(ga.x + xi.x) * tanhf(ga.z + xg.x);
            float hv0 = sigf(ga.w + xo.x) * tanhf(cn0);
            float cn1 = sigf(gb.y + xf.y) * cp1 + sigf(gb.x + xi.y) * tanhf(gb.z + xg.y);
            float hv1 = sigf(gb.w + xo.y) * tanhf(cn1);
            cs[m][jl0] = cn0; cs[m][jl1] = cn1;
            *(float2*)(hn + m * NH + jg0) = make_float2(hv0, hv1);
            hp[hpk_idx(m, jg0)] = f2h2(hv0, hv1);
            *(float2*)(eo + ((size_t)m * NS + tX) * H2 + half_off + jg0) =
                make_float2(hv0, hv1);
        }
        grid_bar();
    }
    if (l == 0) {
        for (int p = tid; p < 1024; p += 256) {
            int m = p >> 4, jj = p & 15;
            d_cfin[m * NH + j0 + jj] = cs[m][jj];
        }
    }
}

// ---------------------------------------------------------------------------
// Persistent decoder: 4 phases/step; phase 3 on fp16 mma. (unchanged from R12)
// ---------------------------------------------------------------------------
__global__ void __launch_bounds__(256)
dec_persistent_kernel(const float* __restrict__ att_W1,
                      const float* __restrict__ att_W2,
                      const float* __restrict__ att_b2) {
    __shared__ float As[16][64];
    __shared__ float Bq[16][17];
    __shared__ float gsm[64][68];
    __shared__ float qs[H3];
    __shared__ float w2s[H3];
    __shared__ float logits[NS];
    __shared__ float wts[NS];
    __shared__ float sred[2];

    int blk = blockIdx.x, tid = threadIdx.x;
    int tx = tid & 15, ty = tid >> 4;
    int aRow = tid >> 2, aCol = (tid & 3) * 4;
    int wid = tid >> 5, lane = tid & 31;
    int warp_m = wid & 3, warp_n = wid >> 2;
    int g = lane >> 2, lt = lane & 3;

    int p = blk * 256 + tid;           // 0..32767
    int pm = p >> 8, pjp = p & 255, pj0 = pjp * 2;
    float c0 = 0.f, c1 = 0.f;
    if (p < 16384) {
        c0 = d_cfin[pm * NH + pj0];
        c1 = d_cfin[pm * NH + pj0 + 1];
        const float* h0 = d_hbuf[0][0];
        d_xpk[hpk_idx(pm, 2048 + pj0)] =
            f2h2(h0[pm * NH + pj0], h0[pm * NH + pj0 + 1]);
    }

    for (int t = 0; t < NSTEPS; t++) {
        const float* h = (t == 0) ? d_hbuf[0][0] : d_hdec[t & 1];

        // ---- Phase 1: q[64,1536] = h[64,512] @ W1[1024:1536, :]  (fp32)
        if (blk < 96) {
            int c0q = blk * 16;
            float acc[4] = {0.f, 0.f, 0.f, 0.f};
            for (int kb = 0; kb < NH; kb += 16) {
                float4 va = __ldcg((const float4*)(h + aRow * NH + kb + aCol));
                As[aCol+0][aRow] = va.x; As[aCol+1][aRow] = va.y;
                As[aCol+2][aRow] = va.z; As[aCol+3][aRow] = va.w;
                Bq[tid >> 4][tid & 15] =
                    att_W1[(size_t)(H2 + kb + (tid >> 4)) * H3 + c0q + (tid & 15)];
                __syncthreads();
#pragma unroll
                for (int k = 0; k < 16; k++) {
                    float b = Bq[k][tx];
#pragma unroll
                    for (int i = 0; i < 4; i++)
                        acc[i] = fmaf(As[k][ty*4 + i], b, acc[i]);
                }
                __syncthreads();
            }
#pragma unroll
            for (int i = 0; i < 4; i++)
                d_q[(ty*4 + i) * H3 + c0q + tx] = acc[i];
        }
        grid_bar();

        // ---- Phase 2: attention (both encoders); writes A fp32 + packed fp16
        {
            int b = blk & 63, e = blk >> 6;
            const float* P   = d_P[e] + (size_t)(b * NS) * H3;
            const float* enc = d_enc[e] + (size_t)(b * NS) * H2;
            for (int j2 = tid; j2 < H3; j2 += 256) {
                qs[j2]  = __ldcg(&d_q[b * H3 + j2]);
                w2s[j2] = att_W2[j2];
            }
            __syncthreads();
            int w = tid >> 5, ln = tid & 31;
            float b2v = att_b2[0];
#pragma unroll
            for (int si = 0; si < 8; si++) {
                int s = w * 8 + si;
                const float* Pr = P + (size_t)s * H3;
                float part = 0.f;
                for (int j2 = ln; j2 < H3; j2 += 32)
                    part += fmaxf(Pr[j2] + qs[j2], 0.f) * w2s[j2];
#pragma unroll
                for (int off = 16; off; off >>= 1)
                    part += __shfl_down_sync(0xffffffffu, part, off);
                if (ln == 0) logits[s] = part + b2v;
            }
            __syncthreads();
            if (tid == 0) {
                float mx = -1e30f;
                for (int s = 0; s < NS; s++) mx = fmaxf(mx, logits[s]);
                sred[0] = mx;
            }
            __syncthreads();
            if (tid < NS) wts[tid] = expf(logits[tid] - sred[0]);
            __syncthreads();
            if (tid == 0) {
                float sm = 0.f;
                for (int s = 0; s < NS; s++) sm += wts[s];
                sred[1] = 1.f / sm;
            }
            __syncthreads();
            float inv = sred[1];
            float* outA = d_Abuf[e] + (size_t)(t * NB + b) * H2;
            for (int chp = tid; chp < 512; chp += 256) {
                int ch = chp * 2;
                float a0 = 0.f, a1 = 0.f;
                const float* ebase = enc + ch;
                for (int s = 0; s < NS; s++) {
                    float2 ev = *(const float2*)(ebase + (size_t)s * H2);
                    float wv = wts[s];
                    a0 += wv * ev.x; a1 += wv * ev.y;
                }
                a0 *= inv; a1 *= inv;
                *(float2*)(outA + ch) = make_float2(a0, a1);
                d_xpk[hpk_idx(b, e * 1024 + ch)] = f2h2(a0, a1);
            }
        }
        grid_bar();

        // ---- Phase 3 (fp16 mma): [A,Ar,h](K=2560 packed) @ WdecPk, K-split x4
        {
            int ksp = blk >> 5, nt2 = blk & 31;
            int j0v = nt2 * 16;
            const uint4* A4 = (const uint4*)d_xpk + warp_m * 32 + lane;
            const uint4* B4 = (const uint4*)d_WdecPk +
                              (size_t)(nt2 * 4 + warp_n * 2) * 32 + lane;
            float acc[4][4];
#pragma unroll
            for (int i = 0; i < 4; i++)
#pragma unroll
                for (int f = 0; f < 4; f++) acc[i][f] = 0.f;

            int k0 = ksp * 40;
#pragma unroll 4
            for (int ks = k0; ks < k0 + 40; ks++) {
                uint4 av = __ldcg(A4 + (size_t)ks * 128);
                uint4 b0 = B4[(size_t)ks * 4096];
                uint4 b1 = B4[(size_t)ks * 4096 + 32];
                MMA16F(acc[0], av, b0.x, b0.y);
                MMA16F(acc[1], av, b0.z, b0.w);
                MMA16F(acc[2], av, b1.x, b1.y);
                MMA16F(acc[3], av, b1.z, b1.w);
            }
#pragma unroll
            for (int j = 0; j < 4; j++) {
                int vloc = warp_n * 32 + j * 8 + lt * 2;
                int m = warp_m * 16 + g;
                gsm[m][vloc]     = acc[j][0];
                gsm[m][vloc + 1] = acc[j][1];
                gsm[m + 8][vloc]     = acc[j][2];
                gsm[m + 8][vloc + 1] = acc[j][3];
            }
            __syncthreads();
            float* gp = d_gpart + (size_t)(ksp * NB) * H4;
            for (int pp = tid; pp < 1024; pp += 256) {
                int m = pp >> 4, jj = pp & 15;
                float4 gv = *(const float4*)&gsm[m][jj * 4];
                *(float4*)(gp + (size_t)m * H4 + (j0v + jj) * 4) = gv;
            }
            __syncthreads();   // gsm reused next step
        }
        grid_bar();

        // ---- Phase 4: gates; threads p<16384 own unit pairs (v-layout partials)
        if (p < 16384) {
            const float* xr = d_tgtW + (size_t)(t * NB + pm) * H4;
            float4 sa = make_float4(0.f, 0.f, 0.f, 0.f);
            float4 sb = make_float4(0.f, 0.f, 0.f, 0.f);
#pragma unroll
            for (int ks = 0; ks < 4; ks++) {
                const float* gpb = d_gpart + (size_t)(ks * NB + pm) * H4 + pj0 * 4;
                float4 va = __ldcg((const float4*)gpb);
                float4 vb = __ldcg((const float4*)(gpb + 4));
                sa.x += va.x; sa.y += va.y; sa.z += va.z; sa.w += va.w;
                sb.x += vb.x; sb.y += vb.y; sb.z += vb.z; sb.w += vb.w;
            }
            float2 xi = *(const float2*)(xr + pj0);
            float2 xf = *(const float2*)(xr + NH + pj0);
            float2 xg = *(const float2*)(xr + 2 * NH + pj0);
            float2 xo = *(const float2*)(xr + 3 * NH + pj0);
            float cn0 = sigf(sa.y + xf.x) * c0 + sigf(sa.x + xi.x) * tanhf(sa.z + xg.x);
            float hv0 = sigf(sa.w + xo.x) * tanhf(cn0);
            float cn1 = sigf(sb.y + xf.y) * c1 + sigf(sb.x + xi.y) * tanhf(sb.z + xg.y);
            float hv1 = sigf(sb.w + xo.y) * tanhf(cn1);
            c0 = cn0; c1 = cn1;
            *(float2*)(d_hdec[(t + 1) & 1] + pm * NH + pj0) = make_float2(hv0, hv1);
            *(float2*)(d_Dbuf + ((size_t)t * NB + pm) * NH + pj0) = make_float2(hv0, hv1);
            d_xpk[hpk_idx(pm, 2048 + pj0)] = f2h2(hv0, hv1);
        }
        grid_bar();
    }
}

// ---------------------------------------------------------------------------
// Assemble classifier input ci[r=b*T+t] = [tgt_e, A, Ar, g, D] (zeros past STEPS)
// ---------------------------------------------------------------------------
__global__ void assemble_kernel(const float* __restrict__ graph_embs) {
    int r = blockIdx.x;
    int b = r >> 6, t = r & 63;
    float* row = d_ci + (size_t)r * CIW;
    bool live = (t < NSTEPS);
    for (int c = threadIdx.x; c < CIW; c += 256) {
        float v;
        if (c < 512)       v = d_tgt_e[((size_t)t * NB + b) * NE + c];
        else if (c < 1536) v = live ? d_Abuf[0][((size_t)t * NB + b) * H2 + (c - 512)]  : 0.f;
        else if (c < 2560) v = live ? d_Abuf[1][((size_t)t * NB + b) * H2 + (c - 1536)] : 0.f;
        else if (c < 2816) v = graph_embs[b * NG + (c - 2560)];
        else               v = live ? d_Dbuf[((size_t)t * NB + b) * NH + (c - 2816)]    : 0.f;
        row[c] = v;
    }
}

// ---------------------------------------------------------------------------
// Host launch
// ---------------------------------------------------------------------------
static float* symaddr(const void* s) {
    void* p = nullptr;
    cudaGetSymbolAddress(&p, s);
    return (float*)p;
}

static void packA(const float* A, uint32_t* Ap, int M, int K, int lda) {
    dim3 g(M / 64, K / 16);
    packA_fast_kernel<<<g, 256>>>(A, Ap, M, K, lda);
}
static void packB(const float* B, uint32_t* Bp, int K, int N, int ldb) {
    dim3 g(K / 16, N / 256);
    packB_fast_kernel<<<g, 256>>>(B, Bp, K, N, ldb);
}
static void gemm_pk(const uint32_t* Ap, const uint32_t* Bp, const float* bias,
                    float* C, int M, int N, int K, int relu) {
    dim3 g(M / 128, N / 128);   // x = M tiles (adjacent CTAs share the B band)
    mma_gemm_pk<<<g, 256>>>(Ap, Bp, bias, C, M, N, K, relu);
}

extern "C" void kernel_launch(void* const* d_in, const int* in_sizes, int n_in,
                              void* d_out, int out_size) {
    const int*   source_data = (const int*)d_in[0];
    const int*   target_data = (const int*)d_in[1];
    const int*   rationales  = (const int*)d_in[2];
    const float* graph_embs  = (const float*)d_in[3];
    const float* src_emb     = (const float*)d_in[4];
    const float* tgt_emb     = (const float*)d_in[5];
    const float* enc_Wih_f   = (const float*)d_in[6];
    const float* enc_Whh_f   = (const float*)d_in[7];
    const float* enc_b_f     = (const float*)d_in[8];
    const float* enc_Wih_b   = (const float*)d_in[9];
    const float* enc_Whh_b   = (const float*)d_in[10];
    const float* enc_b_b     = (const float*)d_in[11];
    const float* dec_Wih     = (const float*)d_in[12];
    const float* dec_Whh     = (const float*)d_in[13];
    const float* dec_b       = (const float*)d_in[14];
    const float* att_W1      = (const float*)d_in[15];
    const float* att_b1      = (const float*)d_in[16];
    const float* att_W2      = (const float*)d_in[17];
    const float* att_b2      = (const float*)d_in[18];
    const float* cls_Wg      = (const float*)d_in[19];
    const float* cls_bg      = (const float*)d_in[20];
    const float* cls_W2      = (const float*)d_in[21];
    const float* cls_b2      = (const float*)d_in[22];
    float* out = (float*)d_out;

    float* p_src_e = symaddr(d_src_e);
    float* p_rat_e = symaddr(d_rat_e);
    float* p_tgt_e = symaddr(d_tgt_e);
    float* p_Xw    = symaddr(d_Xw);
    float* p_enc   = symaddr(d_enc);
    float* p_P     = symaddr(d_P);
    float* p_tgtW  = symaddr(d_tgtW);
    float* p_ci    = symaddr(d_ci);
    float* p_hid   = symaddr(d_hid);
    uint32_t* p_Ap = (uint32_t*)symaddr(d_Ap);
    uint32_t* p_Bp = (uint32_t*)symaddr(d_Bp);
    uint32_t* p_WhhF = (uint32_t*)symaddr(d_WhhPkF);
    uint32_t* p_WhhB = (uint32_t*)symaddr(d_WhhPkB);
    uint32_t* p_Wdec = (uint32_t*)symaddr(d_WdecPk);
    void*  p_bar   = nullptr;
    cudaGetSymbolAddress(&p_bar, g_bar);

    const size_t XW  = (size_t)NS * NB * H4;
    const size_t ENC = (size_t)NB * NS * H2;
    const size_t PP  = (size_t)NB * NS * H3;

    cudaMemsetAsync(p_bar, 0, sizeof(unsigned int));
    zero_state_kernel<<<1024, 256>>>();
    gather_kernel<<<dim3(4096, 3), 256>>>(source_data, target_data, rationales,
                                          src_emb, tgt_emb);

    // gate-v-interleaved packed recurrence weights (fp16)
    packB_gatesv_kernel<<<512, 256>>>(enc_Whh_f, enc_Whh_f, NH, p_WhhF, NH, H4);
    packB_gatesv_kernel<<<512, 256>>>(enc_Whh_b, enc_Whh_b, NH, p_WhhB, NH, H4);
    packB_gatesv_kernel<<<2560, 256>>>(dec_Wih + (size_t)NE * H4, dec_Whh, 2048,
                                       p_Wdec, 2560, H4);

    // x @ Wih + b, hoisted for all 4 encoder LSTMs (packed fp16 mma)
    packA(p_src_e, p_Ap,            4096, NE, NE);
    packA(p_rat_e, p_Ap + AP_SLOT1, 4096, NE, NE);
    packB(enc_Wih_f, p_Bp, NE, H4, H4);
    gemm_pk(p_Ap,            p_Bp, enc_b_f, p_Xw + 0*XW, 4096, H4, NE, 0);
    gemm_pk(p_Ap + AP_SLOT1, p_Bp, enc_b_f, p_Xw + 2*XW, 4096, H4, NE, 0);
    packB(enc_Wih_b, p_Bp, NE, H4, H4);
    gemm_pk(p_Ap,            p_Bp, enc_b_b, p_Xw + 1*XW, 4096, H4, NE, 0);
    gemm_pk(p_Ap + AP_SLOT1, p_Bp, enc_b_b, p_Xw + 3*XW, 4096, H4, NE, 0);

    // tgt_e @ dec_Wih[:E] + dec_b, hoisted for all 32 decoder steps
    packA(p_tgt_e, p_Ap, NSTEPS * NB, NE, NE);
    packB(dec_Wih, p_Bp, NE, H4, H4);           // first E rows
    gemm_pk(p_Ap, p_Bp, dec_b, p_tgtW, NSTEPS * NB, H4, NE, 0);

    // encoder recurrence: persistent, fp16 tensor-core
    enc_persistent_kernel<<<GRID_PERS, 256>>>();

    // attention pre-projection: enc_out @ W1[:2H] + b1
    packA(p_enc + 0*ENC, p_Ap,            4096, H2, H2);
    packA(p_enc + 1*ENC, p_Ap + AP_SLOT1, 4096, H2, H2);
    packB(att_W1, p_Bp, H2, H3, H3);            // first 2H rows
    gemm_pk(p_Ap,            p_Bp, att_b1, p_P + 0*PP, 4096, H3, H2, 0);
    gemm_pk(p_Ap + AP_SLOT1, p_Bp, att_b1, p_P + 1*PP, 4096, H3, H2, 0);

    // decoder recurrence: persistent, fp16 tensor-core phase 3
    dec_persistent_kernel<<<GRID_PERS, 256>>>(att_W1, att_W2, att_b2);

    // classifier
    assemble_kernel<<<4096, 256>>>(graph_embs);
    packA(p_ci, p_Ap, 4096, CIW, CIW);
    packB(cls_Wg, p_Bp, CIW, H2, H2);
    gemm_pk(p_Ap, p_Bp, cls_bg, p_hid, 4096, H2, CIW, 1);
    packA(p_hid, p_Ap, 4096, H2, H2);
    packB(cls_W2, p_Bp, H2, NV, NV);
    gemm_pk(p_Ap, p_Bp, cls_b2, out, 4096, NV, H2, 0);
}